// round 9
// baseline (speedup 1.0000x reference)
#include <cuda_runtime.h>
#include <math.h>

#define BATCH 8
#define NPTS  4096
#define KNN   16
#define CH    64
#define NTILE 16
#define SAMP  256            // NTILE * KNN samples per tile block
#define NBLK  2048           // BATCH * (NPTS / NTILE)

typedef unsigned long long ull;

// ---------------- device scratch (no allocations allowed) ----------------
__device__ float  g_rel[BATCH * NPTS * KNN * 3];        // 6.3 MB relative vectors
__device__ float  g_h1[(size_t)NBLK * CH * SAMP];       // 134 MB pre-BN block-1 activations
__device__ double g_mom[9];                             // rel moments
__device__ float  g_w1f[CH * 3];                        // BN0-folded w1
__device__ float  g_b1f[CH];
__device__ double g_s1[CH];                             // sum h1 per channel
__device__ double g_ss1[CH];                            // sum h1^2 per channel
__device__ float  g_a1[CH];                             // BN1 scale
__device__ float  g_c1[CH];                             // BN1 shift

// ---------------- f32x2 helpers (FFMA2: packed fp32, PTX-only) ----------------
__device__ __forceinline__ ull ffma2(ull a, ull b, ull c) {
    ull d;
    asm("fma.rn.f32x2 %0, %1, %2, %3;" : "=l"(d) : "l"(a), "l"(b), "l"(c));
    return d;
}
__device__ __forceinline__ ull pack2(float lo, float hi) {
    ull r;
    asm("mov.b64 %0, {%1, %2};" : "=l"(r) : "f"(lo), "f"(hi));
    return r;
}
__device__ __forceinline__ void unpack2(ull v, float& lo, float& hi) {
    asm("mov.b64 {%0, %1}, %2;" : "=f"(lo), "=f"(hi) : "l"(v));
}

// ---------------- K0: zero the cross-launch accumulators ----------------
__global__ void k0_init() {
    int t = threadIdx.x;
    if (t < 9)  g_mom[t] = 0.0;
    if (t < CH) { g_s1[t] = 0.0; g_ss1[t] = 0.0; }
}

// ---------------- K1: KNN (ranks 2..17 by LARGEST distance) + rel + rel moments ----
__global__ __launch_bounds__(256) void k1_knn(const float* __restrict__ xyz) {
    extern __shared__ float4 pts[];      // 4096 x (x,y,z,|p|^2) = 64 KB
    __shared__ float sacc[9];
    const int t    = threadIdx.x;
    const int b    = blockIdx.x >> 4;
    const int tile = blockIdx.x & 15;
    const float* xb = xyz + (size_t)b * 3 * NPTS;
    for (int n = t; n < NPTS; n += 256) {
        float x = xb[n], y = xb[NPTS + n], z = xb[2 * NPTS + n];
        pts[n] = make_float4(x, y, z, fmaf(x, x, fmaf(y, y, z * z)));
    }
    if (t < 9) sacc[t] = 0.0f;
    __syncthreads();

    const int i = tile * 256 + t;
    const float4 q = pts[i];

    float bd[17]; int bi[17];
    #pragma unroll
    for (int u = 0; u < 17; ++u) { bd[u] = -1e30f; bi[u] = 0; }
    float cmin = -1e30f; int cpos = 0;

    #pragma unroll 4
    for (int j = 0; j < NPTS; ++j) {
        float4 p = pts[j];
        float dt = fmaf(q.x, p.x, fmaf(q.y, p.y, q.z * p.z));
        float d  = q.w + p.w - 2.0f * dt;
        if (d > cmin) {            // strict >: ties keep earlier (lower) index, like jax top_k
            bd[cpos] = d; bi[cpos] = j;
            cmin = bd[0]; cpos = 0;
            #pragma unroll
            for (int u = 1; u < 17; ++u)
                if (bd[u] < cmin) { cmin = bd[u]; cpos = u; }
        }
    }

    float mval = bd[0]; int mpos = 0;
    #pragma unroll
    for (int u = 1; u < 17; ++u)
        if (bd[u] > mval || (bd[u] == mval && bi[u] < bi[mpos])) { mval = bd[u]; mpos = u; }

    float sx=0,sy=0,sz=0,sxx=0,sxy=0,sxz=0,syy=0,syz=0,szz=0;
    float* outr = g_rel + (size_t)(b * NPTS + i) * (KNN * 3);
    int kk = 0;
    #pragma unroll
    for (int u = 0; u < 17; ++u) {
        if (u == mpos) continue;
        float4 p = pts[bi[u]];
        float rx = p.x - q.x, ry = p.y - q.y, rz = p.z - q.z;
        outr[kk*3+0] = rx; outr[kk*3+1] = ry; outr[kk*3+2] = rz;
        ++kk;
        sx += rx; sy += ry; sz += rz;
        sxx = fmaf(rx,rx,sxx); sxy = fmaf(rx,ry,sxy); sxz = fmaf(rx,rz,sxz);
        syy = fmaf(ry,ry,syy); syz = fmaf(ry,rz,syz); szz = fmaf(rz,rz,szz);
    }
    atomicAdd(&sacc[0],sx);  atomicAdd(&sacc[1],sy);  atomicAdd(&sacc[2],sz);
    atomicAdd(&sacc[3],sxx); atomicAdd(&sacc[4],sxy); atomicAdd(&sacc[5],sxz);
    atomicAdd(&sacc[6],syy); atomicAdd(&sacc[7],syz); atomicAdd(&sacc[8],szz);
    __syncthreads();
    if (t < 9) atomicAdd(&g_mom[t], (double)sacc[t]);
}

// ---------------- K2: fold block-0 BN into w1 (exact, from rel moments) ----------------
__global__ void k2_fold0(const float* __restrict__ w1, const float* __restrict__ b1,
                         const float* __restrict__ gamma, const float* __restrict__ beta) {
    int o = threadIdx.x;
    if (o >= CH) return;
    double inv = 1.0 / ((double)BATCH * NPTS * KNN);
    double m0=g_mom[0]*inv, m1=g_mom[1]*inv, m2=g_mom[2]*inv;
    double Mxx=g_mom[3]*inv, Mxy=g_mom[4]*inv, Mxz=g_mom[5]*inv;
    double Myy=g_mom[6]*inv, Myz=g_mom[7]*inv, Mzz=g_mom[8]*inv;
    double wx=w1[o*3+0], wy=w1[o*3+1], wz=w1[o*3+2], bb=b1[o];
    double wm = wx*m0 + wy*m1 + wz*m2;
    double mu = wm + bb;
    double e2 = wx*wx*Mxx + wy*wy*Myy + wz*wz*Mzz
              + 2.0*(wx*wy*Mxy + wx*wz*Mxz + wy*wz*Myz)
              + 2.0*bb*wm + bb*bb;
    double var = e2 - mu*mu;
    double a = (double)gamma[o] / sqrt(var + 1e-5);
    g_w1f[o*3+0]=(float)(a*wx); g_w1f[o*3+1]=(float)(a*wy); g_w1f[o*3+2]=(float)(a*wz);
    g_b1f[o]=(float)(a*(bb-mu) + (double)beta[o]);
}

// ---------------- K3: g1 = relu(BN0(w1 rel)); h1 = w2 g1 + b2 -> store + stats ----------------
__global__ __launch_bounds__(256, 2) void k3_h1(const float* __restrict__ w2, const float* __restrict__ b2) {
    extern __shared__ float sm3[];
    float* g1s = sm3;                 // CH*SAMP (64 KB)
    float* w2d = sm3 + CH*SAMP;       // CH*CH duplicated pairs: [c][o]{w,w} (32 KB)
    __shared__ float w1fs[CH*3], b1fs[CH], sh1[CH], sq1[CH];
    __shared__ ull  b2p[CH];
    const int t  = threadIdx.x;
    const int b  = blockIdx.x >> 8;
    const int n0 = (blockIdx.x & 255) * NTILE;
    for (int idx = t; idx < CH*CH; idx += 256) {
        int o = idx >> 6, c = idx & 63;             // w2 row-major [o][c]
        float v = w2[idx];
        w2d[(c*CH + o)*2 + 0] = v;
        w2d[(c*CH + o)*2 + 1] = v;
    }
    if (t < CH*3) w1fs[t] = g_w1f[t];
    if (t < CH) { b1fs[t] = g_b1f[t]; float bv = b2[t]; b2p[t] = pack2(bv, bv);
                  sh1[t]=0.f; sq1[t]=0.f; }
    __syncthreads();

    {   // stage 1: g1 for this tile (sample s = n_local*16 + k)
        const int nl = t >> 4, k = t & 15;
        const float* r = g_rel + (size_t)((b*NPTS + n0 + nl)*KNN + k)*3;
        float rx=r[0], ry=r[1], rz=r[2];
        #pragma unroll 16
        for (int o = 0; o < CH; ++o) {
            float h = fmaf(w1fs[o*3], rx, fmaf(w1fs[o*3+1], ry, fmaf(w1fs[o*3+2], rz, b1fs[o])));
            g1s[o*SAMP + t] = fmaxf(h, 0.0f);
        }
    }
    __syncthreads();

    // stage 2: h1 — 4 sample-pairs x 8 channels per thread, packed f32x2
    const int og = t >> 5, sg = t & 31;
    const int o0 = og*8, s0 = sg*8;
    ull acc[4][8];
    #pragma unroll
    for (int j=0;j<8;++j) {
        ull bv = b2p[o0+j];
        #pragma unroll
        for (int i=0;i<4;++i) acc[i][j] = bv;
    }
    for (int c = 0; c < CH; ++c) {
        const ulonglong2* gp = (const ulonglong2*)(g1s + c*SAMP + s0);
        const ulonglong2* wp = (const ulonglong2*)(w2d + (c*CH + o0)*2);
        ulonglong2 g01 = gp[0], g23 = gp[1];
        ulonglong2 w01 = wp[0], w23 = wp[1], w45 = wp[2], w67 = wp[3];
        ull gv[4] = {g01.x, g01.y, g23.x, g23.y};
        ull wv[8] = {w01.x, w01.y, w23.x, w23.y, w45.x, w45.y, w67.x, w67.y};
        #pragma unroll
        for (int i=0;i<4;++i)
            #pragma unroll
            for (int j=0;j<8;++j)
                acc[i][j] = ffma2(gv[i], wv[j], acc[i][j]);
    }
    float* hb = g_h1 + (size_t)blockIdx.x * (CH*SAMP);
    #pragma unroll
    for (int j=0;j<8;++j) {
        float s=0.f, qq=0.f;
        #pragma unroll
        for (int i=0;i<4;++i) {
            float lo, hi; unpack2(acc[i][j], lo, hi);
            s += lo + hi; qq = fmaf(lo,lo,qq); qq = fmaf(hi,hi,qq);
        }
        atomicAdd(&sh1[o0+j], s);
        atomicAdd(&sq1[o0+j], qq);
        ulonglong2* hp = (ulonglong2*)(hb + (o0+j)*SAMP + s0);
        hp[0] = make_ulonglong2(acc[0][j], acc[1][j]);
        hp[1] = make_ulonglong2(acc[2][j], acc[3][j]);
    }
    __syncthreads();
    if (t < CH) { atomicAdd(&g_s1[t], (double)sh1[t]); atomicAdd(&g_ss1[t], (double)sq1[t]); }
}

// ---------------- K3b: finalize block-1 BN affine ----------------
__global__ void k3b_fold1(const float* __restrict__ gamma, const float* __restrict__ beta) {
    int o = threadIdx.x;
    if (o >= CH) return;
    double inv = 1.0 / ((double)BATCH * NPTS * KNN);
    double mu  = g_s1[o] * inv;
    double var = g_ss1[o] * inv - mu*mu;
    double a = (double)gamma[o] / sqrt(var + 1e-5);
    g_a1[o] = (float)a;
    g_c1[o] = (float)((double)beta[o] - a*mu);
}

// ---------------- K4: g2 = relu(BN1(h1)); h2 = w2 g2 + b2; max over k -> out ----------------
__global__ __launch_bounds__(256, 2) void k4_out(const float* __restrict__ w2, const float* __restrict__ b2,
                                                  float* __restrict__ out) {
    extern __shared__ float sm4[];
    float* g2s = sm4;                 // CH*SAMP (64 KB)
    float* w2d = sm4 + CH*SAMP;       // CH*CH duplicated pairs (32 KB)
    __shared__ float a1s[CH], c1s[CH];
    __shared__ ull  b2p[CH];
    __shared__ float mbuf[CH*32];
    const int t  = threadIdx.x;
    const int b  = blockIdx.x >> 8;
    const int n0 = (blockIdx.x & 255) * NTILE;
    for (int idx = t; idx < CH*CH; idx += 256) {
        int o = idx >> 6, c = idx & 63;
        float v = w2[idx];
        w2d[(c*CH + o)*2 + 0] = v;
        w2d[(c*CH + o)*2 + 1] = v;
    }
    if (t < CH) { a1s[t]=g_a1[t]; c1s[t]=g_c1[t]; float bv=b2[t]; b2p[t]=pack2(bv,bv); }
    __syncthreads();

    const float* hb = g_h1 + (size_t)blockIdx.x * (CH*SAMP);
    for (int idx = t*4; idx < CH*SAMP; idx += 256*4) {
        float4 v = *(const float4*)(hb + idx);
        int o = idx >> 8;                       // 4 elems stay inside one 256-wide row
        float a = a1s[o], c = c1s[o];
        v.x = fmaxf(fmaf(a,v.x,c),0.f);
        v.y = fmaxf(fmaf(a,v.y,c),0.f);
        v.z = fmaxf(fmaf(a,v.z,c),0.f);
        v.w = fmaxf(fmaf(a,v.w,c),0.f);
        *(float4*)(g2s + idx) = v;
    }
    __syncthreads();

    const int og = t >> 5, sg = t & 31;
    const int o0 = og*8, s0 = sg*8;
    ull acc[4][8];
    #pragma unroll
    for (int j=0;j<8;++j) {
        ull bv = b2p[o0+j];
        #pragma unroll
        for (int i=0;i<4;++i) acc[i][j] = bv;
    }
    for (int c = 0; c < CH; ++c) {
        const ulonglong2* gp = (const ulonglong2*)(g2s + c*SAMP + s0);
        const ulonglong2* wp = (const ulonglong2*)(w2d + (c*CH + o0)*2);
        ulonglong2 g01 = gp[0], g23 = gp[1];
        ulonglong2 w01 = wp[0], w23 = wp[1], w45 = wp[2], w67 = wp[3];
        ull gv[4] = {g01.x, g01.y, g23.x, g23.y};
        ull wv[8] = {w01.x, w01.y, w23.x, w23.y, w45.x, w45.y, w67.x, w67.y};
        #pragma unroll
        for (int i=0;i<4;++i)
            #pragma unroll
            for (int j=0;j<8;++j)
                acc[i][j] = ffma2(gv[i], wv[j], acc[i][j]);
    }
    // partial max over this thread's 8 k values (4 packed pairs)
    #pragma unroll
    for (int j=0;j<8;++j) {
        float m = -1e30f;
        #pragma unroll
        for (int i=0;i<4;++i) {
            float lo, hi; unpack2(acc[i][j], lo, hi);
            m = fmaxf(m, fmaxf(lo, hi));
        }
        mbuf[(o0+j)*32 + sg] = m;
    }
    __syncthreads();
    // combine the two k-halves (sg and sg^1 share the same n_local)
    if ((sg & 1) == 0) {
        const int n = n0 + (sg >> 1);
        #pragma unroll
        for (int j=0;j<8;++j) {
            int o = o0+j;
            float m = fmaxf(mbuf[o*32 + sg], mbuf[o*32 + sg + 1]);
            out[((size_t)(b*CH + o))*NPTS + n] = m;
        }
    }
}

// ---------------- launch ----------------
extern "C" void kernel_launch(void* const* d_in, const int* in_sizes, int n_in,
                              void* d_out, int out_size) {
    const float* xyz   = (const float*)d_in[0];
    const float* w1    = (const float*)d_in[1];
    const float* b1    = (const float*)d_in[2];
    const float* w2    = (const float*)d_in[3];
    const float* b2    = (const float*)d_in[4];
    const float* gamma = (const float*)d_in[5];
    const float* beta  = (const float*)d_in[6];
    float* out = (float*)d_out;
    (void)in_sizes; (void)n_in; (void)out_size;

    cudaFuncSetAttribute(k1_knn, cudaFuncAttributeMaxDynamicSharedMemorySize, 65536);
    cudaFuncSetAttribute(k3_h1,  cudaFuncAttributeMaxDynamicSharedMemorySize, 98304);
    cudaFuncSetAttribute(k4_out, cudaFuncAttributeMaxDynamicSharedMemorySize, 98304);

    k0_init<<<1, 256>>>();
    k1_knn<<<128, 256, 65536>>>(xyz);
    k2_fold0<<<1, 64>>>(w1, b1, gamma, beta);
    k3_h1<<<NBLK, 256, 98304>>>(w2, b2);
    k3b_fold1<<<1, 64>>>(gamma, beta);
    k4_out<<<NBLK, 256, 98304>>>(w2, b2, out);
}